// round 13
// baseline (speedup 1.0000x reference)
#include <cuda_runtime.h>
#include <cstddef>

#define N_NODES 100000
#define N_EDGES 640000
#define DIM 128
#define ALPHA 0.3f
#define BIN_CAP 64            // P(Poisson(6.4) >= 64) ~ 1e-40: safe hard bound

// ── Allocation-free scratch ─────────────────────────────────────────────
__device__ int  g_count[N_NODES];                       // cursor, then degree
__device__ int2 g_bins[(size_t)N_NODES * BIN_CAP];      // {edge_id, src} per dst bin

// K1: bin edges by dst (R8 scalar form — int2 variant measured neutral/worse).
__global__ void bin_edges(const int* __restrict__ src_idx,
                          const int* __restrict__ dst_idx) {
    int e = blockIdx.x * blockDim.x + threadIdx.x;
    if (e >= N_EDGES) return;
    int d = dst_idx[e];
    int s = src_idx[e];
    int rank = atomicAdd(&g_count[d], 1);
    g_bins[(size_t)d * BIN_CAP + rank] = make_int2(e, s);
}
// After K1, g_count[n] == degree(n).

// K2: one warp per node, clamped-index uniform unroll-4. Every iteration
// issues 8 embedding LDG.128 (duplicated clamped loads hit L1 — same address
// as the genuine last record — so no extra DRAM bytes); 0/1 weights drop the
// duplicates from the sum. Removes the MLP-4/MLP-2 tail paths that R8 ran
// for ~half of all iterations. No scratch writes (R11 lesson).
__global__ void __launch_bounds__(256, 5)
gather_finalize(const float* __restrict__ src_emb,
                const float* __restrict__ dst_emb,
                const float* __restrict__ edge_emb,
                float*       __restrict__ out) {
    int g    = blockIdx.x * blockDim.x + threadIdx.x;
    int n    = g >> 5;
    int lane = g & 31;
    if (n >= N_NODES) return;

    int deg = g_count[n];
    const int2* bin = g_bins + (size_t)n * BIN_CAP;
    size_t off = (size_t)n * DIM + (size_t)lane * 4;

    if (deg == 0) {
        *reinterpret_cast<float4*>(out + off) = make_float4(0.f, 0.f, 0.f, 0.f);
        return;
    }

    // Independent of the gather chain: hoist to overlap.
    float4 de = __ldcs(reinterpret_cast<const float4*>(dst_emb + off));

    float4 acc = make_float4(0.f, 0.f, 0.f, 0.f);
    int degm1 = deg - 1;
    for (int j = 0; j < deg; j += 4) {
        int j1 = min(j + 1, degm1);
        int j2 = min(j + 2, degm1);
        int j3 = min(j + 3, degm1);
        float w1 = (j + 1 <= degm1) ? 1.f : 0.f;
        float w2 = (j + 2 <= degm1) ? 1.f : 0.f;
        float w3 = (j + 3 <= degm1) ? 1.f : 0.f;

        int2 r0 = __ldg(bin + j);
        int2 r1 = __ldg(bin + j1);
        int2 r2 = __ldg(bin + j2);
        int2 r3 = __ldg(bin + j3);

        float4 a0 = __ldg (reinterpret_cast<const float4*>(src_emb  + (size_t)r0.y * DIM) + lane);
        float4 b0 = __ldcs(reinterpret_cast<const float4*>(edge_emb + (size_t)r0.x * DIM) + lane);
        float4 a1 = __ldg (reinterpret_cast<const float4*>(src_emb  + (size_t)r1.y * DIM) + lane);
        float4 b1 = __ldcs(reinterpret_cast<const float4*>(edge_emb + (size_t)r1.x * DIM) + lane);
        float4 a2 = __ldg (reinterpret_cast<const float4*>(src_emb  + (size_t)r2.y * DIM) + lane);
        float4 b2 = __ldcs(reinterpret_cast<const float4*>(edge_emb + (size_t)r2.x * DIM) + lane);
        float4 a3 = __ldg (reinterpret_cast<const float4*>(src_emb  + (size_t)r3.y * DIM) + lane);
        float4 b3 = __ldcs(reinterpret_cast<const float4*>(edge_emb + (size_t)r3.x * DIM) + lane);

        acc.x += (a0.x + b0.x) + w1 * (a1.x + b1.x) + w2 * (a2.x + b2.x) + w3 * (a3.x + b3.x);
        acc.y += (a0.y + b0.y) + w1 * (a1.y + b1.y) + w2 * (a2.y + b2.y) + w3 * (a3.y + b3.y);
        acc.z += (a0.z + b0.z) + w1 * (a1.z + b1.z) + w2 * (a2.z + b2.z) + w3 * (a3.z + b3.z);
        acc.w += (a0.w + b0.w) + w1 * (a1.w + b1.w) + w2 * (a2.w + b2.w) + w3 * (a3.w + b3.w);
    }

    float inv = (1.0f - ALPHA) / (float)deg;
    float4 r;
    r.x = ALPHA * de.x + acc.x * inv;
    r.y = ALPHA * de.y + acc.y * inv;
    r.z = ALPHA * de.z + acc.z * inv;
    r.w = ALPHA * de.w + acc.w * inv;
    *reinterpret_cast<float4*>(out + off) = r;
}

extern "C" void kernel_launch(void* const* d_in, const int* in_sizes, int n_in,
                              void* d_out, int out_size) {
    const float* src_emb  = (const float*)d_in[0];
    const float* dst_emb  = (const float*)d_in[1];
    const float* edge_emb = (const float*)d_in[2];
    const int*   src_idx  = (const int*)d_in[3];
    const int*   dst_idx  = (const int*)d_in[4];
    float* out = (float*)d_out;

    int* d_count;
    cudaGetSymbolAddress((void**)&d_count, g_count);
    cudaMemsetAsync(d_count, 0, N_NODES * sizeof(int));    // graph-legal, no launch

    bin_edges<<<(N_EDGES + 255) / 256, 256>>>(src_idx, dst_idx);

    {
        long long total = (long long)N_NODES * 32;   // one warp per node
        int blocks = (int)((total + 255) / 256);
        gather_finalize<<<blocks, 256>>>(src_emb, dst_emb, edge_emb, out);
    }
}

// round 15
// speedup vs baseline: 1.1959x; 1.1959x over previous
#include <cuda_runtime.h>
#include <cstddef>

#define N_NODES 100000
#define N_EDGES 640000
#define DIM 128
#define ALPHA 0.3f
#define BIN_CAP 64            // P(Poisson(6.4) >= 64) ~ 1e-40: safe hard bound

// ── Allocation-free scratch ─────────────────────────────────────────────
__device__ int  g_count[N_NODES];                       // cursor, then degree
__device__ int2 g_bins[(size_t)N_NODES * BIN_CAP];      // {edge_id, src} per dst bin

// K1: bin edges by dst (R8 scalar form — proven fastest variant).
__global__ void bin_edges(const int* __restrict__ src_idx,
                          const int* __restrict__ dst_idx) {
    int e = blockIdx.x * blockDim.x + threadIdx.x;
    if (e >= N_EDGES) return;
    int d = dst_idx[e];
    int s = src_idx[e];
    int rank = atomicAdd(&g_count[d], 1);
    g_bins[(size_t)d * BIN_CAP + rank] = make_int2(e, s);
}
// After K1, g_count[n] == degree(n).

// K2: EXACT R8 loop body (unroll-4 + 2/1 tails, direct record loads, no
// scratch writes). Proven 92.6us @ 67.7% DRAM. Single change this round:
// 128-thread blocks (launch_bounds(128,10) -> same 40-warp/SM reg ceiling)
// to cut block-retirement granularity 8->4 warps; the straggler warp
// (max of Poisson(6.4) degrees in the block) then strands 3 warps not 7.
__global__ void __launch_bounds__(128, 10)
gather_finalize(const float* __restrict__ src_emb,
                const float* __restrict__ dst_emb,
                const float* __restrict__ edge_emb,
                float*       __restrict__ out) {
    int g    = blockIdx.x * blockDim.x + threadIdx.x;
    int n    = g >> 5;
    int lane = g & 31;
    if (n >= N_NODES) return;

    int deg = g_count[n];
    const int2* bin = g_bins + (size_t)n * BIN_CAP;
    size_t off = (size_t)n * DIM + (size_t)lane * 4;

    if (deg == 0) {
        *reinterpret_cast<float4*>(out + off) = make_float4(0.f, 0.f, 0.f, 0.f);
        return;
    }

    // Independent of the gather chain: hoist to overlap.
    float4 de = __ldcs(reinterpret_cast<const float4*>(dst_emb + off));

    float4 acc = make_float4(0.f, 0.f, 0.f, 0.f);
    int j = 0;
    for (; j + 3 < deg; j += 4) {
        int2 r0 = __ldg(bin + j);
        int2 r1 = __ldg(bin + j + 1);
        int2 r2 = __ldg(bin + j + 2);
        int2 r3 = __ldg(bin + j + 3);
        float4 a0 = __ldg (reinterpret_cast<const float4*>(src_emb  + (size_t)r0.y * DIM) + lane);
        float4 b0 = __ldcs(reinterpret_cast<const float4*>(edge_emb + (size_t)r0.x * DIM) + lane);
        float4 a1 = __ldg (reinterpret_cast<const float4*>(src_emb  + (size_t)r1.y * DIM) + lane);
        float4 b1 = __ldcs(reinterpret_cast<const float4*>(edge_emb + (size_t)r1.x * DIM) + lane);
        float4 a2 = __ldg (reinterpret_cast<const float4*>(src_emb  + (size_t)r2.y * DIM) + lane);
        float4 b2 = __ldcs(reinterpret_cast<const float4*>(edge_emb + (size_t)r2.x * DIM) + lane);
        float4 a3 = __ldg (reinterpret_cast<const float4*>(src_emb  + (size_t)r3.y * DIM) + lane);
        float4 b3 = __ldcs(reinterpret_cast<const float4*>(edge_emb + (size_t)r3.x * DIM) + lane);
        acc.x += ((a0.x + b0.x) + (a1.x + b1.x)) + ((a2.x + b2.x) + (a3.x + b3.x));
        acc.y += ((a0.y + b0.y) + (a1.y + b1.y)) + ((a2.y + b2.y) + (a3.y + b3.y));
        acc.z += ((a0.z + b0.z) + (a1.z + b1.z)) + ((a2.z + b2.z) + (a3.z + b3.z));
        acc.w += ((a0.w + b0.w) + (a1.w + b1.w)) + ((a2.w + b2.w) + (a3.w + b3.w));
    }
    if (j + 1 < deg) {                       // 2-edge tail
        int2 r0 = __ldg(bin + j);
        int2 r1 = __ldg(bin + j + 1);
        float4 a0 = __ldg (reinterpret_cast<const float4*>(src_emb  + (size_t)r0.y * DIM) + lane);
        float4 b0 = __ldcs(reinterpret_cast<const float4*>(edge_emb + (size_t)r0.x * DIM) + lane);
        float4 a1 = __ldg (reinterpret_cast<const float4*>(src_emb  + (size_t)r1.y * DIM) + lane);
        float4 b1 = __ldcs(reinterpret_cast<const float4*>(edge_emb + (size_t)r1.x * DIM) + lane);
        acc.x += (a0.x + b0.x) + (a1.x + b1.x);
        acc.y += (a0.y + b0.y) + (a1.y + b1.y);
        acc.z += (a0.z + b0.z) + (a1.z + b1.z);
        acc.w += (a0.w + b0.w) + (a1.w + b1.w);
        j += 2;
    }
    if (j < deg) {
        int2 r0 = __ldg(bin + j);
        float4 a0 = __ldg (reinterpret_cast<const float4*>(src_emb  + (size_t)r0.y * DIM) + lane);
        float4 b0 = __ldcs(reinterpret_cast<const float4*>(edge_emb + (size_t)r0.x * DIM) + lane);
        acc.x += a0.x + b0.x;
        acc.y += a0.y + b0.y;
        acc.z += a0.z + b0.z;
        acc.w += a0.w + b0.w;
    }

    float inv = (1.0f - ALPHA) / (float)deg;
    float4 r;
    r.x = ALPHA * de.x + acc.x * inv;
    r.y = ALPHA * de.y + acc.y * inv;
    r.z = ALPHA * de.z + acc.z * inv;
    r.w = ALPHA * de.w + acc.w * inv;
    *reinterpret_cast<float4*>(out + off) = r;
}

extern "C" void kernel_launch(void* const* d_in, const int* in_sizes, int n_in,
                              void* d_out, int out_size) {
    const float* src_emb  = (const float*)d_in[0];
    const float* dst_emb  = (const float*)d_in[1];
    const float* edge_emb = (const float*)d_in[2];
    const int*   src_idx  = (const int*)d_in[3];
    const int*   dst_idx  = (const int*)d_in[4];
    float* out = (float*)d_out;

    int* d_count;
    cudaGetSymbolAddress((void**)&d_count, g_count);
    cudaMemsetAsync(d_count, 0, N_NODES * sizeof(int));    // graph-legal, no launch

    bin_edges<<<(N_EDGES + 255) / 256, 256>>>(src_idx, dst_idx);

    {
        long long total = (long long)N_NODES * 32;   // one warp per node
        int blocks = (int)((total + 127) / 128);     // 128-thread blocks (single change)
        gather_finalize<<<blocks, 128>>>(src_emb, dst_emb, edge_emb, out);
    }
}

// round 16
// speedup vs baseline: 1.2039x; 1.0067x over previous
#include <cuda_runtime.h>
#include <cstddef>

#define N_NODES 100000
#define N_EDGES 640000
#define DIM 128
#define ALPHA 0.3f
#define BIN_CAP 64            // P(Poisson(6.4) >= 64) ~ 1e-40: safe hard bound

// ── Allocation-free scratch ─────────────────────────────────────────────
__device__ int  g_count[N_NODES];                       // cursor, then degree
__device__ int2 g_bins[(size_t)N_NODES * BIN_CAP];      // {edge_id, src} per dst bin

// K1: bin edges by dst (R8 scalar form — proven fastest variant).
__global__ void bin_edges(const int* __restrict__ src_idx,
                          const int* __restrict__ dst_idx) {
    int e = blockIdx.x * blockDim.x + threadIdx.x;
    if (e >= N_EDGES) return;
    int d = dst_idx[e];
    int s = src_idx[e];
    int rank = atomicAdd(&g_count[d], 1);
    g_bins[(size_t)d * BIN_CAP + rank] = make_int2(e, s);
}
// After K1, g_count[n] == degree(n).

// K2: EXACT R8 loop body (unroll-4 + 2/1 tails, direct record loads, no
// scratch writes). R15 confirmed the straggler-retirement mechanism:
// 256->128 threads/block gave +4.5% occ, -3.9us. This round extends it:
// 64-thread blocks (launch_bounds(64,20) -> same 40-warp/SM ceiling,
// 20 blocks/SM < 32 structural limit). Straggler now strands 1 warp, not 3.
__global__ void __launch_bounds__(64, 20)
gather_finalize(const float* __restrict__ src_emb,
                const float* __restrict__ dst_emb,
                const float* __restrict__ edge_emb,
                float*       __restrict__ out) {
    int g    = blockIdx.x * blockDim.x + threadIdx.x;
    int n    = g >> 5;
    int lane = g & 31;
    if (n >= N_NODES) return;

    int deg = g_count[n];
    const int2* bin = g_bins + (size_t)n * BIN_CAP;
    size_t off = (size_t)n * DIM + (size_t)lane * 4;

    if (deg == 0) {
        *reinterpret_cast<float4*>(out + off) = make_float4(0.f, 0.f, 0.f, 0.f);
        return;
    }

    // Independent of the gather chain: hoist to overlap.
    float4 de = __ldcs(reinterpret_cast<const float4*>(dst_emb + off));

    float4 acc = make_float4(0.f, 0.f, 0.f, 0.f);
    int j = 0;
    for (; j + 3 < deg; j += 4) {
        int2 r0 = __ldg(bin + j);
        int2 r1 = __ldg(bin + j + 1);
        int2 r2 = __ldg(bin + j + 2);
        int2 r3 = __ldg(bin + j + 3);
        float4 a0 = __ldg (reinterpret_cast<const float4*>(src_emb  + (size_t)r0.y * DIM) + lane);
        float4 b0 = __ldcs(reinterpret_cast<const float4*>(edge_emb + (size_t)r0.x * DIM) + lane);
        float4 a1 = __ldg (reinterpret_cast<const float4*>(src_emb  + (size_t)r1.y * DIM) + lane);
        float4 b1 = __ldcs(reinterpret_cast<const float4*>(edge_emb + (size_t)r1.x * DIM) + lane);
        float4 a2 = __ldg (reinterpret_cast<const float4*>(src_emb  + (size_t)r2.y * DIM) + lane);
        float4 b2 = __ldcs(reinterpret_cast<const float4*>(edge_emb + (size_t)r2.x * DIM) + lane);
        float4 a3 = __ldg (reinterpret_cast<const float4*>(src_emb  + (size_t)r3.y * DIM) + lane);
        float4 b3 = __ldcs(reinterpret_cast<const float4*>(edge_emb + (size_t)r3.x * DIM) + lane);
        acc.x += ((a0.x + b0.x) + (a1.x + b1.x)) + ((a2.x + b2.x) + (a3.x + b3.x));
        acc.y += ((a0.y + b0.y) + (a1.y + b1.y)) + ((a2.y + b2.y) + (a3.y + b3.y));
        acc.z += ((a0.z + b0.z) + (a1.z + b1.z)) + ((a2.z + b2.z) + (a3.z + b3.z));
        acc.w += ((a0.w + b0.w) + (a1.w + b1.w)) + ((a2.w + b2.w) + (a3.w + b3.w));
    }
    if (j + 1 < deg) {                       // 2-edge tail
        int2 r0 = __ldg(bin + j);
        int2 r1 = __ldg(bin + j + 1);
        float4 a0 = __ldg (reinterpret_cast<const float4*>(src_emb  + (size_t)r0.y * DIM) + lane);
        float4 b0 = __ldcs(reinterpret_cast<const float4*>(edge_emb + (size_t)r0.x * DIM) + lane);
        float4 a1 = __ldg (reinterpret_cast<const float4*>(src_emb  + (size_t)r1.y * DIM) + lane);
        float4 b1 = __ldcs(reinterpret_cast<const float4*>(edge_emb + (size_t)r1.x * DIM) + lane);
        acc.x += (a0.x + b0.x) + (a1.x + b1.x);
        acc.y += (a0.y + b0.y) + (a1.y + b1.y);
        acc.z += (a0.z + b0.z) + (a1.z + b1.z);
        acc.w += (a0.w + b0.w) + (a1.w + b1.w);
        j += 2;
    }
    if (j < deg) {
        int2 r0 = __ldg(bin + j);
        float4 a0 = __ldg (reinterpret_cast<const float4*>(src_emb  + (size_t)r0.y * DIM) + lane);
        float4 b0 = __ldcs(reinterpret_cast<const float4*>(edge_emb + (size_t)r0.x * DIM) + lane);
        acc.x += a0.x + b0.x;
        acc.y += a0.y + b0.y;
        acc.z += a0.z + b0.z;
        acc.w += a0.w + b0.w;
    }

    float inv = (1.0f - ALPHA) / (float)deg;
    float4 r;
    r.x = ALPHA * de.x + acc.x * inv;
    r.y = ALPHA * de.y + acc.y * inv;
    r.z = ALPHA * de.z + acc.z * inv;
    r.w = ALPHA * de.w + acc.w * inv;
    *reinterpret_cast<float4*>(out + off) = r;
}

extern "C" void kernel_launch(void* const* d_in, const int* in_sizes, int n_in,
                              void* d_out, int out_size) {
    const float* src_emb  = (const float*)d_in[0];
    const float* dst_emb  = (const float*)d_in[1];
    const float* edge_emb = (const float*)d_in[2];
    const int*   src_idx  = (const int*)d_in[3];
    const int*   dst_idx  = (const int*)d_in[4];
    float* out = (float*)d_out;

    int* d_count;
    cudaGetSymbolAddress((void**)&d_count, g_count);
    cudaMemsetAsync(d_count, 0, N_NODES * sizeof(int));    // graph-legal, no launch

    bin_edges<<<(N_EDGES + 255) / 256, 256>>>(src_idx, dst_idx);

    {
        long long total = (long long)N_NODES * 32;   // one warp per node
        int blocks = (int)((total + 63) / 64);       // 64-thread blocks (single change)
        gather_finalize<<<blocks, 64>>>(src_emb, dst_emb, edge_emb, out);
    }
}